// round 2
// baseline (speedup 1.0000x reference)
#include <cuda_runtime.h>
#include <cuda_bf16.h>
#include <math.h>

// ---------------- static scratch (no allocations allowed) ----------------
#define T_ 8
#define B_ 128
#define N_ (T_*B_)   // 1024

__device__ float g_y1[N_*64*32*32];   // conv1 out            (268 MB)
__device__ float g_s1[N_*64*16*16];   // pooled spikes L1     (67 MB)
__device__ float g_y2[N_*128*16*16];  // conv2 out            (134 MB)
__device__ float g_s2[N_*128*8*8];    // pooled spikes L2     (33.5 MB)
__device__ float g_z1[N_*256];        // fc1 out
__device__ float g_s3[N_*256];        // LIF spikes L3

__device__ double g_p1sum[64*64],  g_p1sq[64*64];
__device__ double g_p2sum[128*32], g_p2sq[128*32];
__device__ float  g_scale1[64], g_shift1[64];
__device__ float  g_scale2[128], g_shift2[128];

// LIF step exactly matching reference arithmetic:
//   v = v + (x - v)/2 ; s = (v - 1 >= 0) ; v = v * (1 - s)
#define LIF_STEP(v, x, s)                         \
    {                                             \
        v = v + (x - v) * 0.5f;                   \
        s = (v >= 1.0f) ? 1.0f : 0.0f;            \
        v = (v >= 1.0f) ? 0.0f : v;               \
    }

// ---------------- conv1: 3->64, 32x32, pad 1 ----------------
// one block per image; 256 threads, 4 pixels/thread, 8 output chans per reg-block
__global__ void __launch_bounds__(256) conv1_kernel(const float* __restrict__ x,
                                                    const float* __restrict__ w)
{
    __shared__ float s_in[3*34*34];   // padded input
    __shared__ float s_w[64*27];
    const int n = blockIdx.x, tid = threadIdx.x;

    for (int i = tid; i < 3*34*34; i += 256) s_in[i] = 0.0f;
    __syncthreads();
    for (int i = tid; i < 3*1024; i += 256) {
        int ci = i >> 10, p = i & 1023, h = p >> 5, wc = p & 31;
        s_in[ci*1156 + (h+1)*34 + (wc+1)] = x[n*3072 + i];
    }
    for (int i = tid; i < 1728; i += 256) s_w[i] = w[i];
    __syncthreads();

    int hh[4], ww[4];
#pragma unroll
    for (int j = 0; j < 4; j++) { int p = tid + j*256; hh[j] = p >> 5; ww[j] = p & 31; }

#pragma unroll 1
    for (int cb = 0; cb < 64; cb += 8) {
        float acc[8][4];
#pragma unroll
        for (int u = 0; u < 8; u++)
#pragma unroll
            for (int j = 0; j < 4; j++) acc[u][j] = 0.0f;

#pragma unroll
        for (int ci = 0; ci < 3; ci++)
#pragma unroll
        for (int kh = 0; kh < 3; kh++)
#pragma unroll
        for (int kw = 0; kw < 3; kw++) {
            const int k = ci*9 + kh*3 + kw;
            float wr[8];
#pragma unroll
            for (int u = 0; u < 8; u++) wr[u] = s_w[(cb+u)*27 + k];
#pragma unroll
            for (int j = 0; j < 4; j++) {
                float xv = s_in[ci*1156 + (hh[j]+kh)*34 + (ww[j]+kw)];
#pragma unroll
                for (int u = 0; u < 8; u++) acc[u][j] += wr[u] * xv;
            }
        }
#pragma unroll
        for (int u = 0; u < 8; u++)
#pragma unroll
            for (int j = 0; j < 4; j++)
                g_y1[(n*64 + cb + u)*1024 + tid + j*256] = acc[u][j];
    }
}

// ---------------- BN stats (deterministic, two-stage, fp64) ----------------
__global__ void __launch_bounds__(256) stats1_kernel()
{
    const int c = blockIdx.x, slab = blockIdx.y, tid = threadIdx.x;
    double ts = 0.0, tq = 0.0;
    for (int i = tid; i < 16*1024; i += 256) {
        int n = slab*16 + (i >> 10), p = i & 1023;
        double v = (double)g_y1[(n*64 + c)*1024 + p];
        ts += v; tq += v*v;
    }
    __shared__ double ss[256], sq[256];
    ss[tid] = ts; sq[tid] = tq; __syncthreads();
    for (int s = 128; s > 0; s >>= 1) {
        if (tid < s) { ss[tid] += ss[tid+s]; sq[tid] += sq[tid+s]; }
        __syncthreads();
    }
    if (tid == 0) { g_p1sum[c*64 + slab] = ss[0]; g_p1sq[c*64 + slab] = sq[0]; }
}

__global__ void __launch_bounds__(256) stats2_kernel()
{
    const int c = blockIdx.x, slab = blockIdx.y, tid = threadIdx.x;
    double ts = 0.0, tq = 0.0;
    for (int i = tid; i < 32*256; i += 256) {
        int n = slab*32 + (i >> 8), p = i & 255;
        double v = (double)g_y2[(n*128 + c)*256 + p];
        ts += v; tq += v*v;
    }
    __shared__ double ss[256], sq[256];
    ss[tid] = ts; sq[tid] = tq; __syncthreads();
    for (int s = 128; s > 0; s >>= 1) {
        if (tid < s) { ss[tid] += ss[tid+s]; sq[tid] += sq[tid+s]; }
        __syncthreads();
    }
    if (tid == 0) { g_p2sum[c*32 + slab] = ss[0]; g_p2sq[c*32 + slab] = sq[0]; }
}

__global__ void finalize1_kernel(const float* __restrict__ g, const float* __restrict__ b)
{
    int c = threadIdx.x;  // 64 threads
    double s = 0.0, q = 0.0;
    for (int i = 0; i < 64; i++) { s += g_p1sum[c*64 + i]; q += g_p1sq[c*64 + i]; }
    const double cnt = 1048576.0;
    double m = s / cnt, var = q / cnt - m*m;
    double sc = (double)g[c] / sqrt(var + 1e-5);
    g_scale1[c] = (float)sc;
    g_shift1[c] = (float)((double)b[c] - m*sc);
}

__global__ void finalize2_kernel(const float* __restrict__ g, const float* __restrict__ b)
{
    int c = threadIdx.x;  // 128 threads
    double s = 0.0, q = 0.0;
    for (int i = 0; i < 32; i++) { s += g_p2sum[c*32 + i]; q += g_p2sq[c*32 + i]; }
    const double cnt = 262144.0;
    double m = s / cnt, var = q / cnt - m*m;
    double sc = (double)g[c] / sqrt(var + 1e-5);
    g_scale2[c] = (float)sc;
    g_shift2[c] = (float)((double)b[c] - m*sc);
}

// ---------------- BN affine + LIF over T + 2x2 avgpool, layer 1 ----------------
__global__ void __launch_bounds__(256) lifpool1_kernel()
{
    const int bc = blockIdx.x;                 // 8192 = 128*64
    const int c = bc & 63, b = bc >> 6;
    const int tid = threadIdx.x;
    const int hg = tid >> 4, wg = tid & 15;
    const float sc = g_scale1[c], sh = g_shift1[c];
    float v0 = 0, v1 = 0, v2 = 0, v3 = 0;
#pragma unroll
    for (int t = 0; t < T_; t++) {
        const int n = t*B_ + b;
        const int base = (n*64 + c)*1024 + (hg*2)*32 + wg*2;
        float2 r0 = *reinterpret_cast<const float2*>(g_y1 + base);
        float2 r1 = *reinterpret_cast<const float2*>(g_y1 + base + 32);
        float x00 = r0.x*sc + sh, x01 = r0.y*sc + sh;
        float x10 = r1.x*sc + sh, x11 = r1.y*sc + sh;
        float s00, s01, s10, s11;
        LIF_STEP(v0, x00, s00); LIF_STEP(v1, x01, s01);
        LIF_STEP(v2, x10, s10); LIF_STEP(v3, x11, s11);
        g_s1[(n*64 + c)*256 + hg*16 + wg] = (s00 + s01 + s10 + s11)*0.25f;
    }
}

// ---------------- conv2: 64->128, 16x16, pad 1 ----------------
// one block per (image pair, 16-output-chan chunk); weights LDS.128-packed
__global__ void __launch_bounds__(256) conv2_kernel(const float* __restrict__ w)
{
    extern __shared__ float sm[];
    float* s_in = sm;                  // 2*64*18*18 = 41472 floats
    float* s_w  = sm + 41472;          // 16*64*12   = 12288 floats (9 taps + pad 3)
    const int pair = blockIdx.x, chunk = blockIdx.y, tid = threadIdx.x;
    const int n0 = pair*2, co0 = chunk*16;

    for (int i = tid; i < 41472; i += 256) s_in[i] = 0.0f;
    __syncthreads();
    for (int i = tid; i < 64*256; i += 256) {
        int ci = i >> 8, p = i & 255, hh = p >> 4, wc = p & 15;
        int so = ci*324 + (hh+1)*18 + (wc+1);
        s_in[so]         = g_s1[(n0*64 + ci)*256 + p];
        s_in[20736 + so] = g_s1[((n0+1)*64 + ci)*256 + p];
    }
    for (int i = tid; i < 16*576; i += 256) {
        int co = i / 576, r = i - co*576, ci = r / 9, k = r - ci*9;
        s_w[(co*64 + ci)*12 + k] = w[(co0 + co)*576 + r];
    }
    __syncthreads();

    const int hh = tid >> 4, wc = tid & 15;
    const int ibase = hh*18 + wc;
    float acc[16][2];
#pragma unroll
    for (int co = 0; co < 16; co++) { acc[co][0] = 0.0f; acc[co][1] = 0.0f; }

#pragma unroll 1
    for (int ci = 0; ci < 64; ci++) {
        float xr0[9], xr1[9];
#pragma unroll
        for (int kh = 0; kh < 3; kh++)
#pragma unroll
        for (int kw = 0; kw < 3; kw++) {
            int o = ci*324 + ibase + kh*18 + kw;
            xr0[kh*3 + kw] = s_in[o];
            xr1[kh*3 + kw] = s_in[20736 + o];
        }
#pragma unroll
        for (int co = 0; co < 16; co++) {
            const float4* wp = reinterpret_cast<const float4*>(s_w + (co*64 + ci)*12);
            float4 wa = wp[0], wb = wp[1];
            float w8 = s_w[(co*64 + ci)*12 + 8];
            float a0 = acc[co][0], a1 = acc[co][1];
            a0 += xr0[0]*wa.x; a1 += xr1[0]*wa.x;
            a0 += xr0[1]*wa.y; a1 += xr1[1]*wa.y;
            a0 += xr0[2]*wa.z; a1 += xr1[2]*wa.z;
            a0 += xr0[3]*wa.w; a1 += xr1[3]*wa.w;
            a0 += xr0[4]*wb.x; a1 += xr1[4]*wb.x;
            a0 += xr0[5]*wb.y; a1 += xr1[5]*wb.y;
            a0 += xr0[6]*wb.z; a1 += xr1[6]*wb.z;
            a0 += xr0[7]*wb.w; a1 += xr1[7]*wb.w;
            a0 += xr0[8]*w8;   a1 += xr1[8]*w8;
            acc[co][0] = a0; acc[co][1] = a1;
        }
    }
#pragma unroll
    for (int co = 0; co < 16; co++) {
        g_y2[(n0*128 + co0 + co)*256 + tid]       = acc[co][0];
        g_y2[((n0+1)*128 + co0 + co)*256 + tid]   = acc[co][1];
    }
}

// ---------------- BN affine + LIF + pool, layer 2 ----------------
__global__ void __launch_bounds__(256) lifpool2_kernel()
{
    const int tid = threadIdx.x;
    const int u = blockIdx.x*4 + (tid >> 6);   // (b,c) unit; 16384 total
    const int c = u & 127, b = u >> 7;
    const int pix = tid & 63;
    const int hg = pix >> 3, wg = pix & 7;
    const float sc = g_scale2[c], sh = g_shift2[c];
    float v0 = 0, v1 = 0, v2 = 0, v3 = 0;
#pragma unroll
    for (int t = 0; t < T_; t++) {
        const int n = t*B_ + b;
        const int base = (n*128 + c)*256 + (hg*2)*16 + wg*2;
        float2 r0 = *reinterpret_cast<const float2*>(g_y2 + base);
        float2 r1 = *reinterpret_cast<const float2*>(g_y2 + base + 16);
        float x00 = r0.x*sc + sh, x01 = r0.y*sc + sh;
        float x10 = r1.x*sc + sh, x11 = r1.y*sc + sh;
        float s00, s01, s10, s11;
        LIF_STEP(v0, x00, s00); LIF_STEP(v1, x01, s01);
        LIF_STEP(v2, x10, s10); LIF_STEP(v3, x11, s11);
        g_s2[(n*128 + c)*64 + hg*8 + wg] = (s00 + s01 + s10 + s11)*0.25f;
    }
}

// ---------------- fc1: [1024,8192] x [256,8192]^T -> [1024,256] ----------------
__global__ void __launch_bounds__(256) fc1_kernel(const float* __restrict__ W)
{
    __shared__ float As[32][65];
    __shared__ float Bs[32][33];
    const int bm0 = blockIdx.x*64, bn0 = blockIdx.y*32, tid = threadIdx.x;
    const int ty = tid >> 4, tx = tid & 15;
    float acc[4][2] = {{0,0},{0,0},{0,0},{0,0}};
    float aR[8], bR[4];

#pragma unroll
    for (int l = 0; l < 8; l++) { int e = tid + l*256; aR[l] = g_s2[(bm0 + (e>>5))*8192 + (e&31)]; }
#pragma unroll
    for (int l = 0; l < 4; l++) { int e = tid + l*256; bR[l] = W[(bn0 + (e>>5))*8192 + (e&31)]; }

    for (int k0 = 0; k0 < 8192; k0 += 32) {
#pragma unroll
        for (int l = 0; l < 8; l++) { int e = tid + l*256; As[e&31][e>>5] = aR[l]; }
#pragma unroll
        for (int l = 0; l < 4; l++) { int e = tid + l*256; Bs[e&31][e>>5] = bR[l]; }
        __syncthreads();
        const int k1 = k0 + 32;
        if (k1 < 8192) {
#pragma unroll
            for (int l = 0; l < 8; l++) { int e = tid + l*256; aR[l] = g_s2[(bm0 + (e>>5))*8192 + k1 + (e&31)]; }
#pragma unroll
            for (int l = 0; l < 4; l++) { int e = tid + l*256; bR[l] = W[(bn0 + (e>>5))*8192 + k1 + (e&31)]; }
        }
#pragma unroll
        for (int kk = 0; kk < 32; kk++) {
            float a0 = As[kk][ty*4+0], a1 = As[kk][ty*4+1];
            float a2 = As[kk][ty*4+2], a3 = As[kk][ty*4+3];
            float b0 = Bs[kk][tx*2+0], b1 = Bs[kk][tx*2+1];
            acc[0][0] += a0*b0; acc[0][1] += a0*b1;
            acc[1][0] += a1*b0; acc[1][1] += a1*b1;
            acc[2][0] += a2*b0; acc[2][1] += a2*b1;
            acc[3][0] += a3*b0; acc[3][1] += a3*b1;
        }
        __syncthreads();
    }
#pragma unroll
    for (int i = 0; i < 4; i++)
#pragma unroll
        for (int j = 0; j < 2; j++)
            g_z1[(bm0 + ty*4 + i)*256 + bn0 + tx*2 + j] = acc[i][j];
}

// ---------------- LIF on fc1 output ----------------
__global__ void __launch_bounds__(256) lif_fc_kernel()
{
    const int gid = blockIdx.x*256 + threadIdx.x;   // 32768
    const int o = gid & 255, b = gid >> 8;
    float v = 0.0f;
#pragma unroll
    for (int t = 0; t < T_; t++) {
        const int idx = (t*B_ + b)*256 + o;
        float x = g_z1[idx], s;
        LIF_STEP(v, x, s);
        g_s3[idx] = s;
    }
}

// ---------------- fc2 + bias ----------------
__global__ void __launch_bounds__(256) fc2_kernel(const float* __restrict__ w2,
                                                  const float* __restrict__ b2,
                                                  float* __restrict__ out)
{
    const int gid = blockIdx.x*256 + threadIdx.x;
    if (gid >= N_*10) return;
    const int smp = gid / 10, o = gid - smp*10;
    const float4* xs = reinterpret_cast<const float4*>(g_s3 + smp*256);
    const float4* ws = reinterpret_cast<const float4*>(w2 + o*256);
    float acc = 0.0f;
#pragma unroll 8
    for (int i = 0; i < 64; i++) {
        float4 a = xs[i], wv = ws[i];
        acc += a.x*wv.x; acc += a.y*wv.y; acc += a.z*wv.z; acc += a.w*wv.w;
    }
    out[gid] = acc + b2[o];
}

// ---------------- launcher ----------------
extern "C" void kernel_launch(void* const* d_in, const int* in_sizes, int n_in,
                              void* d_out, int out_size)
{
    const float* x    = (const float*)d_in[0];
    const float* c1w  = (const float*)d_in[1];
    const float* bn1g = (const float*)d_in[2];
    const float* bn1b = (const float*)d_in[3];
    const float* c2w  = (const float*)d_in[4];
    const float* bn2g = (const float*)d_in[5];
    const float* bn2b = (const float*)d_in[6];
    const float* fc1w = (const float*)d_in[7];
    const float* fc2w = (const float*)d_in[8];
    const float* fc2b = (const float*)d_in[9];
    float* out = (float*)d_out;

    cudaFuncSetAttribute(conv2_kernel, cudaFuncAttributeMaxDynamicSharedMemorySize, 215040);

    conv1_kernel<<<1024, 256>>>(x, c1w);
    stats1_kernel<<<dim3(64, 64), 256>>>();
    finalize1_kernel<<<1, 64>>>(bn1g, bn1b);
    lifpool1_kernel<<<8192, 256>>>();

    conv2_kernel<<<dim3(512, 8), 256, 215040>>>(c2w);
    stats2_kernel<<<dim3(128, 32), 256>>>();
    finalize2_kernel<<<1, 128>>>(bn2g, bn2b);
    lifpool2_kernel<<<4096, 256>>>();

    fc1_kernel<<<dim3(16, 8), 256>>>(fc1w);
    lif_fc_kernel<<<128, 256>>>();
    fc2_kernel<<<40, 256>>>(fc2w, fc2b, out);
}

// round 4
// speedup vs baseline: 2.6289x; 2.6289x over previous
#include <cuda_runtime.h>
#include <cuda_bf16.h>
#include <math.h>
#include <stdint.h>

#define T_ 8
#define B_ 128
#define N_ 1024

// ---------------- static scratch ----------------
__device__ float g_y1[N_*64*32*32];    // conv1 out (268 MB)
__device__ float g_s1[N_*64*16*16];    // pooled spikes L1
__device__ float g_y2[N_*128*16*16];   // conv2 out (134 MB)
__device__ float g_s2[N_*128*8*8];     // pooled spikes L2  (== A rows for fc1)
__device__ float g_s3[N_*256];         // LIF spikes L3
__device__ float g_z1p[8*N_*256];      // fc1 K-split partials (8 slices)

__device__ __nv_bfloat16 g_a2[(size_t)2048*9*8192];   // conv2 im2col tiles, ldmatrix-swizzled
__device__ __nv_bfloat16 g_b2[9*3*8192];              // conv2 weight tiles [kc][split]
__device__ __nv_bfloat16 g_afc[(size_t)8*128*8192];   // fc1 A tiles
__device__ __nv_bfloat16 g_bfc[(size_t)2*128*3*8192]; // fc1 B tiles [nt][kc][split]

__device__ double g_p1sum[64*64],  g_p1sq[64*64];
__device__ double g_p2sum[128*32], g_p2sq[128*32];
__device__ float  g_scale1[64], g_shift1[64];
__device__ float  g_scale2[128], g_shift2[128];

// LIF step exactly matching reference arithmetic
#define LIF_STEP(v, x, s)                         \
    {                                             \
        v = v + (x - v) * 0.5f;                   \
        s = (v >= 1.0f) ? 1.0f : 0.0f;            \
        v = (v >= 1.0f) ? 0.0f : v;               \
    }

__device__ __forceinline__ unsigned smem_u32(const void* p) {
    return (unsigned)__cvta_generic_to_shared(p);
}
__device__ __forceinline__ unsigned pack_bf2(__nv_bfloat16 a, __nv_bfloat16 b) {
    return (unsigned)__bfloat16_as_ushort(a) | ((unsigned)__bfloat16_as_ushort(b) << 16);
}

// ---------------- portable tensor-core helpers (sm_80-class PTX) ----------------
#define CP16(dst, src) \
    asm volatile("cp.async.cg.shared.global [%0], [%1], 16;" :: "r"(dst), "l"(src))
#define CP_COMMIT() asm volatile("cp.async.commit_group;" ::: "memory")
#define CP_WAIT1()  asm volatile("cp.async.wait_group 1;" ::: "memory")
#define CP_WAIT0()  asm volatile("cp.async.wait_group 0;" ::: "memory")

__device__ __forceinline__ void ldsm4(unsigned& r0, unsigned& r1, unsigned& r2, unsigned& r3,
                                      unsigned a) {
    asm volatile("ldmatrix.sync.aligned.m8n8.x4.shared.b16 {%0,%1,%2,%3}, [%4];"
                 : "=r"(r0), "=r"(r1), "=r"(r2), "=r"(r3) : "r"(a));
}
__device__ __forceinline__ void mma_bf16(float* c, const unsigned* a, const unsigned* b) {
    asm volatile("mma.sync.aligned.m16n8k16.row.col.f32.bf16.bf16.f32 "
                 "{%0,%1,%2,%3}, {%4,%5,%6,%7}, {%8,%9}, {%0,%1,%2,%3};"
                 : "+f"(c[0]), "+f"(c[1]), "+f"(c[2]), "+f"(c[3])
                 : "r"(a[0]), "r"(a[1]), "r"(a[2]), "r"(a[3]), "r"(b[0]), "r"(b[1]));
}

// ---------------- conv1: 3->64, 32x32, pad 1 (scalar fp32) ----------------
__global__ void __launch_bounds__(256) conv1_kernel(const float* __restrict__ x,
                                                    const float* __restrict__ w)
{
    __shared__ float s_in[3*34*34];
    __shared__ float s_w[64*27];
    const int n = blockIdx.x, tid = threadIdx.x;

    for (int i = tid; i < 3*34*34; i += 256) s_in[i] = 0.0f;
    __syncthreads();
    for (int i = tid; i < 3*1024; i += 256) {
        int ci = i >> 10, p = i & 1023, h = p >> 5, wc = p & 31;
        s_in[ci*1156 + (h+1)*34 + (wc+1)] = x[n*3072 + i];
    }
    for (int i = tid; i < 1728; i += 256) s_w[i] = w[i];
    __syncthreads();

    int hh[4], ww[4];
#pragma unroll
    for (int j = 0; j < 4; j++) { int p = tid + j*256; hh[j] = p >> 5; ww[j] = p & 31; }

#pragma unroll 1
    for (int cb = 0; cb < 64; cb += 8) {
        float acc[8][4];
#pragma unroll
        for (int u = 0; u < 8; u++)
#pragma unroll
            for (int j = 0; j < 4; j++) acc[u][j] = 0.0f;

#pragma unroll
        for (int ci = 0; ci < 3; ci++)
#pragma unroll
        for (int kh = 0; kh < 3; kh++)
#pragma unroll
        for (int kw = 0; kw < 3; kw++) {
            const int k = ci*9 + kh*3 + kw;
            float wr[8];
#pragma unroll
            for (int u = 0; u < 8; u++) wr[u] = s_w[(cb+u)*27 + k];
#pragma unroll
            for (int j = 0; j < 4; j++) {
                float xv = s_in[ci*1156 + (hh[j]+kh)*34 + (ww[j]+kw)];
#pragma unroll
                for (int u = 0; u < 8; u++) acc[u][j] += wr[u] * xv;
            }
        }
#pragma unroll
        for (int u = 0; u < 8; u++)
#pragma unroll
            for (int j = 0; j < 4; j++)
                g_y1[(n*64 + cb + u)*1024 + tid + j*256] = acc[u][j];
    }
}

// ---------------- BN stats ----------------
__global__ void __launch_bounds__(256) stats1_kernel()
{
    const int c = blockIdx.x, slab = blockIdx.y, tid = threadIdx.x;
    double ds = 0.0, dq = 0.0;
    for (int ib = 0; ib < 64; ib += 8) {
        float fs = 0.0f, fq = 0.0f;
#pragma unroll
        for (int j = 0; j < 8; j++) {
            int i = (ib + j)*256 + tid;
            int n = slab*16 + (i >> 10), p = i & 1023;
            float v = g_y1[(n*64 + c)*1024 + p];
            fs += v; fq += v*v;
        }
        ds += (double)fs; dq += (double)fq;
    }
    __shared__ double ss[256], sq[256];
    ss[tid] = ds; sq[tid] = dq; __syncthreads();
    for (int s = 128; s > 0; s >>= 1) {
        if (tid < s) { ss[tid] += ss[tid+s]; sq[tid] += sq[tid+s]; }
        __syncthreads();
    }
    if (tid == 0) { g_p1sum[c*64 + slab] = ss[0]; g_p1sq[c*64 + slab] = sq[0]; }
}

__global__ void __launch_bounds__(256) stats2_kernel()
{
    const int c = blockIdx.x, slab = blockIdx.y, tid = threadIdx.x;
    double ds = 0.0, dq = 0.0;
    for (int ib = 0; ib < 32; ib += 8) {
        float fs = 0.0f, fq = 0.0f;
#pragma unroll
        for (int j = 0; j < 8; j++) {
            int it = ib + j;
            float v = g_y2[((slab*32 + it)*128 + c)*256 + tid];
            fs += v; fq += v*v;
        }
        ds += (double)fs; dq += (double)fq;
    }
    __shared__ double ss[256], sq[256];
    ss[tid] = ds; sq[tid] = dq; __syncthreads();
    for (int s = 128; s > 0; s >>= 1) {
        if (tid < s) { ss[tid] += ss[tid+s]; sq[tid] += sq[tid+s]; }
        __syncthreads();
    }
    if (tid == 0) { g_p2sum[c*32 + slab] = ss[0]; g_p2sq[c*32 + slab] = sq[0]; }
}

__global__ void finalize1_kernel(const float* __restrict__ g, const float* __restrict__ b)
{
    int c = threadIdx.x;
    double s = 0.0, q = 0.0;
    for (int i = 0; i < 64; i++) { s += g_p1sum[c*64 + i]; q += g_p1sq[c*64 + i]; }
    const double cnt = 1048576.0;
    double m = s / cnt, var = q / cnt - m*m;
    double sc = (double)g[c] / sqrt(var + 1e-5);
    g_scale1[c] = (float)sc;
    g_shift1[c] = (float)((double)b[c] - m*sc);
}

__global__ void finalize2_kernel(const float* __restrict__ g, const float* __restrict__ b)
{
    int c = threadIdx.x;
    double s = 0.0, q = 0.0;
    for (int i = 0; i < 32; i++) { s += g_p2sum[c*32 + i]; q += g_p2sq[c*32 + i]; }
    const double cnt = 262144.0;
    double m = s / cnt, var = q / cnt - m*m;
    double sc = (double)g[c] / sqrt(var + 1e-5);
    g_scale2[c] = (float)sc;
    g_shift2[c] = (float)((double)b[c] - m*sc);
}

// ---------------- BN + LIF + pool, layer 1 ----------------
__global__ void __launch_bounds__(256) lifpool1_kernel()
{
    const int bc = blockIdx.x;
    const int c = bc & 63, b = bc >> 6;
    const int tid = threadIdx.x;
    const int hg = tid >> 4, wg = tid & 15;
    const float sc = g_scale1[c], sh = g_shift1[c];
    float v0 = 0, v1 = 0, v2 = 0, v3 = 0;
#pragma unroll
    for (int t = 0; t < T_; t++) {
        const int n = t*B_ + b;
        const int base = (n*64 + c)*1024 + (hg*2)*32 + wg*2;
        float2 r0 = *reinterpret_cast<const float2*>(g_y1 + base);
        float2 r1 = *reinterpret_cast<const float2*>(g_y1 + base + 32);
        float x00 = r0.x*sc + sh, x01 = r0.y*sc + sh;
        float x10 = r1.x*sc + sh, x11 = r1.y*sc + sh;
        float s00, s01, s10, s11;
        LIF_STEP(v0, x00, s00); LIF_STEP(v1, x01, s01);
        LIF_STEP(v2, x10, s10); LIF_STEP(v3, x11, s11);
        g_s1[(n*64 + c)*256 + hg*16 + wg] = (s00 + s01 + s10 + s11)*0.25f;
    }
}

// ---------------- conv2 weight 3-split into swizzled bf16 tiles ----------------
__global__ void __launch_bounds__(256) prep_conv2_w_kernel(const float* __restrict__ w)
{
    int gid = blockIdx.x*256 + threadIdx.x;     // 9*128*4 = 4608
    if (gid >= 4608) return;
    int c32 = gid & 3, co = (gid >> 2) & 127, kc = gid >> 9;
    unsigned hi[8], mid[8], lo[8];
    __nv_bfloat16 h2[2], m2[2], l2[2];
#pragma unroll
    for (int e = 0; e < 16; e++) {
        int k = kc*64 + c32*16 + e;
        float wv = w[co*576 + k];
        __nv_bfloat16 h = __float2bfloat16(wv);
        float r1 = wv - __bfloat162float(h);
        __nv_bfloat16 m = __float2bfloat16(r1);
        float r2 = r1 - __bfloat162float(m);
        __nv_bfloat16 l = __float2bfloat16(r2);
        h2[e & 1] = h; m2[e & 1] = m; l2[e & 1] = l;
        if (e & 1) {
            hi[e >> 1] = pack_bf2(h2[0], h2[1]);
            mid[e >> 1] = pack_bf2(m2[0], m2[1]);
            lo[e >> 1] = pack_bf2(l2[0], l2[1]);
        }
    }
    int r = co;
    int ua = r*8 + ((2*c32) ^ (r & 7));
    int ub = r*8 + ((2*c32 + 1) ^ (r & 7));
    for (int s = 0; s < 3; s++) {
        unsigned* src = (s == 0) ? hi : (s == 1) ? mid : lo;
        __nv_bfloat16* base = g_b2 + ((size_t)kc*3 + s)*8192;
        *(uint4*)(base + ua*8) = make_uint4(src[0], src[1], src[2], src[3]);
        *(uint4*)(base + ub*8) = make_uint4(src[4], src[5], src[6], src[7]);
    }
}

// ---------------- im2col for conv2 into swizzled bf16 tiles ----------------
__global__ void __launch_bounds__(256) im2col2_kernel()
{
    int gid = blockIdx.x*256 + threadIdx.x;     // 9*4*262144
    int m = gid & 262143;
    int rest = gid >> 18;
    int c32 = rest & 3, kc = rest >> 2;
    int n = m >> 8, p = m & 255, h = p >> 4, w = p & 15;
    int mt = m >> 7, r = m & 127;
    unsigned pk[8];
    __nv_bfloat16 v2[2];
#pragma unroll
    for (int e = 0; e < 16; e++) {
        int k = kc*64 + c32*16 + e;
        int ci = k / 9, t9 = k - ci*9, kh = t9 / 3, kw = t9 - kh*3;
        int ih = h + kh - 1, iw = w + kw - 1;
        float v = 0.0f;
        if ((unsigned)ih < 16u && (unsigned)iw < 16u)
            v = g_s1[((n*64 + ci) << 8) + (ih << 4) + iw];
        v2[e & 1] = __float2bfloat16(v);
        if (e & 1) pk[e >> 1] = pack_bf2(v2[0], v2[1]);
    }
    __nv_bfloat16* base = g_a2 + ((size_t)mt*9 + kc)*8192;
    int ua = r*8 + ((2*c32) ^ (r & 7));
    int ub = r*8 + ((2*c32 + 1) ^ (r & 7));
    *(uint4*)(base + ua*8) = make_uint4(pk[0], pk[1], pk[2], pk[3]);
    *(uint4*)(base + ub*8) = make_uint4(pk[4], pk[5], pk[6], pk[7]);
}

// ---------------- conv2 GEMM: [262144 x 576*3] x [128 x ...]^T via mma.sync ----------------
// 128x128 tile, 8 warps (32m x 64n each), BK=64, cp.async double buffer.
__global__ void __launch_bounds__(256) conv2_gemm_kernel()
{
    extern __shared__ char dsm[];
    const unsigned sbase = smem_u32(dsm);
    const int tid = threadIdx.x, lane = tid & 31, wid = tid >> 5;
    const int mt = blockIdx.x;
    const int m0 = (wid & 3) * 32, n0 = (wid >> 2) * 64;

    float acc[2][8][4];
#pragma unroll
    for (int f = 0; f < 2; f++)
#pragma unroll
        for (int nf = 0; nf < 8; nf++)
#pragma unroll
            for (int q = 0; q < 4; q++) acc[f][nf][q] = 0.0f;

    // prefetch chunk kc into stage st: A 16KB + B 48KB
    {
        unsigned dst = sbase;
        const char* ag = (const char*)(g_a2 + ((size_t)mt*9 + 0)*8192);
#pragma unroll
        for (int i = 0; i < 4; i++)
            CP16(dst + (unsigned)(tid + i*256)*16, ag + (size_t)(tid + i*256)*16);
        const char* bg = (const char*)(g_b2);
#pragma unroll
        for (int i = 0; i < 12; i++)
            CP16(dst + 16384u + (unsigned)(tid + i*256)*16, bg + (size_t)(tid + i*256)*16);
        CP_COMMIT();
    }

#pragma unroll 1
    for (int kc = 0; kc < 9; kc++) {
        const int cur = kc & 1;
        if (kc < 8) {
            unsigned dst = sbase + (unsigned)(cur ^ 1)*65536u;
            const char* ag = (const char*)(g_a2 + ((size_t)mt*9 + kc + 1)*8192);
#pragma unroll
            for (int i = 0; i < 4; i++)
                CP16(dst + (unsigned)(tid + i*256)*16, ag + (size_t)(tid + i*256)*16);
            const char* bg = (const char*)(g_b2 + (size_t)(kc + 1)*3*8192);
#pragma unroll
            for (int i = 0; i < 12; i++)
                CP16(dst + 16384u + (unsigned)(tid + i*256)*16, bg + (size_t)(tid + i*256)*16);
            CP_COMMIT();
            CP_WAIT1();
        } else {
            CP_WAIT0();
        }
        __syncthreads();

        const unsigned sA = sbase + (unsigned)cur*65536u;
        const unsigned sB = sA + 16384u;

        unsigned afr[4][2][4];
#pragma unroll
        for (int ks = 0; ks < 4; ks++)
#pragma unroll
            for (int f = 0; f < 2; f++) {
                int row = m0 + f*16 + (lane & 15);
                int c16 = ks*2 + (lane >> 4);
                unsigned ad = sA + (unsigned)((row*8 + (c16 ^ (row & 7)))*16);
                ldsm4(afr[ks][f][0], afr[ks][f][1], afr[ks][f][2], afr[ks][f][3], ad);
            }

#pragma unroll 1
        for (int s = 0; s < 3; s++) {
            const unsigned bb = sB + (unsigned)s*16384u;
#pragma unroll
            for (int ks = 0; ks < 4; ks++) {
                unsigned bfr[8][2];
#pragma unroll
                for (int nb = 0; nb < 4; nb++) {
                    int row = n0 + nb*16 + (lane & 7) + ((lane >> 4) << 3);
                    int c16 = ks*2 + ((lane >> 3) & 1);
                    unsigned ad = bb + (unsigned)((row*8 + (c16 ^ (row & 7)))*16);
                    unsigned r0, r1, r2, r3;
                    ldsm4(r0, r1, r2, r3, ad);
                    bfr[2*nb][0] = r0; bfr[2*nb][1] = r1;
                    bfr[2*nb+1][0] = r2; bfr[2*nb+1][1] = r3;
                }
#pragma unroll
                for (int f = 0; f < 2; f++)
#pragma unroll
                    for (int nf = 0; nf < 8; nf++)
                        mma_bf16(acc[f][nf], afr[ks][f], bfr[nf]);
            }
        }
        __syncthreads();
    }

    // epilogue: D[m][co] -> g_y2[(n_img*128+co)*256 + p], m = n_img*256 + p
    const int rbase = m0 + (lane >> 2);
    const int cbase = n0 + 2*(lane & 3);
#pragma unroll
    for (int f = 0; f < 2; f++)
#pragma unroll
        for (int half = 0; half < 2; half++) {
            int m = mt*128 + rbase + f*16 + half*8;
            int nimg = m >> 8, p = m & 255;
            float* op = g_y2 + (size_t)nimg*128*256 + p;
#pragma unroll
            for (int nf = 0; nf < 8; nf++) {
                int co = cbase + nf*8;
                op[(size_t)co*256]       = acc[f][nf][half*2];
                op[(size_t)(co+1)*256]   = acc[f][nf][half*2 + 1];
            }
        }
}

// ---------------- BN + LIF + pool, layer 2 ----------------
__global__ void __launch_bounds__(256) lifpool2_kernel()
{
    const int tid = threadIdx.x;
    const int u = blockIdx.x*4 + (tid >> 6);
    const int c = u & 127, b = u >> 7;
    const int pix = tid & 63;
    const int hg = pix >> 3, wg = pix & 7;
    const float sc = g_scale2[c], sh = g_shift2[c];
    float v0 = 0, v1 = 0, v2 = 0, v3 = 0;
#pragma unroll
    for (int t = 0; t < T_; t++) {
        const int n = t*B_ + b;
        const int base = (n*128 + c)*256 + (hg*2)*16 + wg*2;
        float2 r0 = *reinterpret_cast<const float2*>(g_y2 + base);
        float2 r1 = *reinterpret_cast<const float2*>(g_y2 + base + 16);
        float x00 = r0.x*sc + sh, x01 = r0.y*sc + sh;
        float x10 = r1.x*sc + sh, x11 = r1.y*sc + sh;
        float s00, s01, s10, s11;
        LIF_STEP(v0, x00, s00); LIF_STEP(v1, x01, s01);
        LIF_STEP(v2, x10, s10); LIF_STEP(v3, x11, s11);
        g_s2[(n*128 + c)*64 + hg*8 + wg] = (s00 + s01 + s10 + s11)*0.25f;
    }
}

// ---------------- fc1 A repack ----------------
__global__ void __launch_bounds__(256) repack_fcA_kernel()
{
    int gid = blockIdx.x*256 + threadIdx.x;    // 524288
    int c32 = gid & 3, r = (gid >> 2) & 127, kc = (gid >> 9) & 127, mt = gid >> 16;
    int m = mt*128 + r;
    unsigned pk[8];
    __nv_bfloat16 v2[2];
#pragma unroll
    for (int e = 0; e < 16; e++) {
        int k = kc*64 + c32*16 + e;
        v2[e & 1] = __float2bfloat16(g_s2[(size_t)m*8192 + k]);
        if (e & 1) pk[e >> 1] = pack_bf2(v2[0], v2[1]);
    }
    __nv_bfloat16* base = g_afc + ((size_t)mt*128 + kc)*8192;
    int ua = r*8 + ((2*c32) ^ (r & 7));
    int ub = r*8 + ((2*c32 + 1) ^ (r & 7));
    *(uint4*)(base + ua*8) = make_uint4(pk[0], pk[1], pk[2], pk[3]);
    *(uint4*)(base + ub*8) = make_uint4(pk[4], pk[5], pk[6], pk[7]);
}

// ---------------- fc1 weight 3-split ----------------
__global__ void __launch_bounds__(256) prep_fc1_w_kernel(const float* __restrict__ w)
{
    int gid = blockIdx.x*256 + threadIdx.x;    // 131072
    int c32 = gid & 3, r = (gid >> 2) & 127, kc = (gid >> 9) & 127, nt = gid >> 16;
    int co = nt*128 + r;
    unsigned hi[8], mid[8], lo[8];
    __nv_bfloat16 h2[2], m2[2], l2[2];
#pragma unroll
    for (int e = 0; e < 16; e++) {
        int k = kc*64 + c32*16 + e;
        float wv = w[(size_t)co*8192 + k];
        __nv_bfloat16 h = __float2bfloat16(wv);
        float r1 = wv - __bfloat162float(h);
        __nv_bfloat16 m = __float2bfloat16(r1);
        float r2 = r1 - __bfloat162float(m);
        __nv_bfloat16 l = __float2bfloat16(r2);
        h2[e & 1] = h; m2[e & 1] = m; l2[e & 1] = l;
        if (e & 1) {
            hi[e >> 1] = pack_bf2(h2[0], h2[1]);
            mid[e >> 1] = pack_bf2(m2[0], m2[1]);
            lo[e >> 1] = pack_bf2(l2[0], l2[1]);
        }
    }
    int ua = r*8 + ((2*c32) ^ (r & 7));
    int ub = r*8 + ((2*c32 + 1) ^ (r & 7));
    for (int s = 0; s < 3; s++) {
        unsigned* src = (s == 0) ? hi : (s == 1) ? mid : lo;
        __nv_bfloat16* base = g_bfc + (((size_t)nt*128 + kc)*3 + s)*8192;
        *(uint4*)(base + ua*8) = make_uint4(src[0], src[1], src[2], src[3]);
        *(uint4*)(base + ub*8) = make_uint4(src[4], src[5], src[6], src[7]);
    }
}

// ---------------- fc1 GEMM with K-split 8 ----------------
__global__ void __launch_bounds__(256) fc1_gemm_kernel()
{
    extern __shared__ char dsm[];
    const unsigned sbase = smem_u32(dsm);
    const int tid = threadIdx.x, lane = tid & 31, wid = tid >> 5;
    const int mt = blockIdx.x, nt = blockIdx.y, ksl = blockIdx.z;
    const int m0 = (wid & 3) * 32, n0 = (wid >> 2) * 64;
    const int kc0 = ksl*16;

    float acc[2][8][4];
#pragma unroll
    for (int f = 0; f < 2; f++)
#pragma unroll
        for (int nf = 0; nf < 8; nf++)
#pragma unroll
            for (int q = 0; q < 4; q++) acc[f][nf][q] = 0.0f;

    {
        unsigned dst = sbase;
        const char* ag = (const char*)(g_afc + ((size_t)mt*128 + kc0)*8192);
#pragma unroll
        for (int i = 0; i < 4; i++)
            CP16(dst + (unsigned)(tid + i*256)*16, ag + (size_t)(tid + i*256)*16);
        const char* bg = (const char*)(g_bfc + ((size_t)nt*128 + kc0)*3*8192);
#pragma unroll
        for (int i = 0; i < 12; i++)
            CP16(dst + 16384u + (unsigned)(tid + i*256)*16, bg + (size_t)(tid + i*256)*16);
        CP_COMMIT();
    }

#pragma unroll 1
    for (int j = 0; j < 16; j++) {
        const int cur = j & 1;
        if (j < 15) {
            const int kc = kc0 + j + 1;
            unsigned dst = sbase + (unsigned)(cur ^ 1)*65536u;
            const char* ag = (const char*)(g_afc + ((size_t)mt*128 + kc)*8192);
#pragma unroll
            for (int i = 0; i < 4; i++)
                CP16(dst + (unsigned)(tid + i*256)*16, ag + (size_t)(tid + i*256)*16);
            const char* bg = (const char*)(g_bfc + ((size_t)nt*128 + kc)*3*8192);
#pragma unroll
            for (int i = 0; i < 12; i++)
                CP16(dst + 16384u + (unsigned)(tid + i*256)*16, bg + (size_t)(tid + i*256)*16);
            CP_COMMIT();
            CP_WAIT1();
        } else {
            CP_WAIT0();
        }
        __syncthreads();

        const unsigned sA = sbase + (unsigned)cur*65536u;
        const unsigned sB = sA + 16384u;

        unsigned afr[4][2][4];
#pragma unroll
        for (int ks = 0; ks < 4; ks++)
#pragma unroll
            for (int f = 0; f < 2; f++) {
                int row = m0 + f*16 + (lane & 15);
                int c16 = ks*2 + (lane >> 4);
                unsigned ad = sA + (unsigned)((row*8 + (c16 ^ (row & 7)))*16);
                ldsm4(afr[ks][f][0], afr[ks][f][1], afr[ks][f][2], afr[ks][f][3], ad);
            }

#pragma unroll 1
        for (int s = 0; s < 3; s++) {
            const unsigned bb = sB + (unsigned)s*16384u;
#pragma unroll
            for (int ks = 0; ks < 4; ks++) {
                unsigned bfr[8][2];
#pragma unroll
                for (int nb = 0; nb < 4; nb++) {
                    int row = n0 + nb*16 + (lane & 7) + ((lane >> 4) << 3);
                    int c16 = ks*2 + ((lane >> 3) & 1);
                    unsigned ad = bb + (unsigned)((row*8 + (c16 ^ (row & 7)))*16);
                    unsigned r0, r1, r2, r3;
                    ldsm4(r0, r1, r2, r3, ad);
                    bfr[2*nb][0] = r0; bfr[2*nb][1] = r1;
                    bfr[2*nb+1][0] = r2; bfr[2*nb+1][1] = r3;
                }
#pragma unroll
                for (int f = 0; f < 2; f++)
#pragma unroll
                    for (int nf = 0; nf < 8; nf++)
                        mma_bf16(acc[f][nf], afr[ks][f], bfr[nf]);
            }
        }
        __syncthreads();
    }

    // epilogue: partial D[m][o] -> g_z1p[ksl][m*256 + nt*128 + col]
    const int rbase = m0 + (lane >> 2);
    const int cbase = n0 + 2*(lane & 3);
    float* outp = g_z1p + (size_t)ksl*262144;
#pragma unroll
    for (int f = 0; f < 2; f++)
#pragma unroll
        for (int half = 0; half < 2; half++) {
            int m = mt*128 + rbase + f*16 + half*8;
            float* op = outp + (size_t)m*256 + nt*128;
#pragma unroll
            for (int nf = 0; nf < 8; nf++) {
                int col = cbase + nf*8;
                op[col]     = acc[f][nf][half*2];
                op[col + 1] = acc[f][nf][half*2 + 1];
            }
        }
}

// ---------------- K-split reduce + LIF on fc1 output ----------------
__global__ void __launch_bounds__(256) lif_fc_kernel()
{
    const int gid = blockIdx.x*256 + threadIdx.x;   // 32768
    const int o = gid & 255, b = gid >> 8;
    const int S = 262144;
    float v = 0.0f;
#pragma unroll
    for (int t = 0; t < T_; t++) {
        const int idx = (t*B_ + b)*256 + o;
        float x = g_z1p[idx];
        x += g_z1p[S + idx];   x += g_z1p[2*S + idx]; x += g_z1p[3*S + idx];
        x += g_z1p[4*S + idx]; x += g_z1p[5*S + idx]; x += g_z1p[6*S + idx];
        x += g_z1p[7*S + idx];
        float s;
        LIF_STEP(v, x, s);
        g_s3[idx] = s;
    }
}

// ---------------- fc2 + bias ----------------
__global__ void __launch_bounds__(256) fc2_kernel(const float* __restrict__ w2,
                                                  const float* __restrict__ b2,
                                                  float* __restrict__ out)
{
    const int gid = blockIdx.x*256 + threadIdx.x;
    if (gid >= N_*10) return;
    const int smp = gid / 10, o = gid - smp*10;
    const float4* xs = reinterpret_cast<const float4*>(g_s3 + smp*256);
    const float4* ws = reinterpret_cast<const float4*>(w2 + o*256);
    float acc = 0.0f;
#pragma unroll 8
    for (int i = 0; i < 64; i++) {
        float4 a = xs[i], wv = ws[i];
        acc += a.x*wv.x; acc += a.y*wv.y; acc += a.z*wv.z; acc += a.w*wv.w;
    }
    out[gid] = acc + b2[o];
}

// ---------------- launcher ----------------
extern "C" void kernel_launch(void* const* d_in, const int* in_sizes, int n_in,
                              void* d_out, int out_size)
{
    const float* x    = (const float*)d_in[0];
    const float* c1w  = (const float*)d_in[1];
    const float* bn1g = (const float*)d_in[2];
    const float* bn1b = (const float*)d_in[3];
    const float* c2w  = (const float*)d_in[4];
    const float* bn2g = (const float*)d_in[5];
    const float* bn2b = (const float*)d_in[6];
    const float* fc1w = (const float*)d_in[7];
    const float* fc2w = (const float*)d_in[8];
    const float* fc2b = (const float*)d_in[9];
    float* out = (float*)d_out;

    cudaFuncSetAttribute(conv2_gemm_kernel, cudaFuncAttributeMaxDynamicSharedMemorySize, 131072);
    cudaFuncSetAttribute(fc1_gemm_kernel,   cudaFuncAttributeMaxDynamicSharedMemorySize, 131072);

    conv1_kernel<<<1024, 256>>>(x, c1w);
    stats1_kernel<<<dim3(64, 64), 256>>>();
    finalize1_kernel<<<1, 64>>>(bn1g, bn1b);
    lifpool1_kernel<<<8192, 256>>>();

    prep_conv2_w_kernel<<<18, 256>>>(c2w);
    im2col2_kernel<<<36864, 256>>>();
    conv2_gemm_kernel<<<2048, 256, 131072>>>();

    stats2_kernel<<<dim3(128, 32), 256>>>();
    finalize2_kernel<<<1, 128>>>(bn2g, bn2b);
    lifpool2_kernel<<<4096, 256>>>();

    repack_fcA_kernel<<<2048, 256>>>();
    prep_fc1_w_kernel<<<512, 256>>>(fc1w);
    fc1_gemm_kernel<<<dim3(8, 2, 8), 256, 131072>>>();

    lif_fc_kernel<<<128, 256>>>();
    fc2_kernel<<<40, 256>>>(fc2w, fc2b, out);
}